// round 2
// baseline (speedup 1.0000x reference)
#include <cuda_runtime.h>
#include <math.h>

#define NN 50000
#define EE 800000
#define DD 128
#define GROWS 32

// Scratch (allocation-free rule: __device__ globals)
__device__ float g_hw[(size_t)NN * DD];   // h @ W (raw, gathered by scatter)
__device__ float g_agg[(size_t)NN * DD];  // aggregation accumulator / next-layer input
__device__ float g_deg[NN];
__device__ float g_dinv[NN];
__device__ float g_norm[EE];

// ---------------------------------------------------------------------------
// degree / norm precompute
// ---------------------------------------------------------------------------
__global__ void k_init_deg(float* deg, int n) {
    int i = blockIdx.x * blockDim.x + threadIdx.x;
    if (i < n) deg[i] = 1.0f;  // self-loop
}

__global__ void k_count_deg(const int* __restrict__ dst, float* deg, int e) {
    int i = blockIdx.x * blockDim.x + threadIdx.x;
    if (i < e) {
        float* a = deg + dst[i];
        asm volatile("red.global.add.f32 [%0], %1;" :: "l"(a), "f"(1.0f) : "memory");
    }
}

__global__ void k_dinv(const float* __restrict__ deg, float* dinv, int n) {
    int i = blockIdx.x * blockDim.x + threadIdx.x;
    if (i < n) dinv[i] = rsqrtf(deg[i]);
}

__global__ void k_norm(const int* __restrict__ src, const int* __restrict__ dst,
                       const float* __restrict__ dinv, float* __restrict__ norm, int e) {
    int i = blockIdx.x * blockDim.x + threadIdx.x;
    if (i < e) norm[i] = dinv[src[i]] * dinv[dst[i]];
}

// ---------------------------------------------------------------------------
// GEMM: out_rows x 128 @ 128x128, fp32.
//   hw[row]  = h[row] @ W                      (raw product, for edge gather)
//   agg[row] = bias + hw[row]*dinv[row]^2      (self-loop term, aggregation init)
//              (+ x[row] when ADDX, for the final residual into d_out)
//   RELU applies to the INPUT h (folds previous layer's activation).
// 128 threads: thread = output column; 32 rows per block, register accumulators.
// ---------------------------------------------------------------------------
template <bool RELU, bool ADDX>
__global__ void k_gemm(const float* __restrict__ H, const float* __restrict__ W,
                       const float* __restrict__ bias, const float* __restrict__ dinv,
                       const float* __restrict__ xres,
                       float* __restrict__ hw, float* __restrict__ agg, int n) {
    extern __shared__ float sm[];
    float* Wsm = sm;              // 128*128 floats = 64KB
    float* Hsm = sm + DD * DD;    // 32*128 floats  = 16KB
    const int tid = threadIdx.x;  // 0..127
    const int row0 = blockIdx.x * GROWS;

    // Stage W (vectorized)
    const float4* W4 = reinterpret_cast<const float4*>(W);
    float4* Wsm4 = reinterpret_cast<float4*>(Wsm);
#pragma unroll
    for (int i = 0; i < (DD * DD / 4) / 128; i++)  // 32
        Wsm4[i * 128 + tid] = W4[i * 128 + tid];

    // Stage 32 H rows (vectorized, ReLU fused, tail-guarded)
    const float4* H4 = reinterpret_cast<const float4*>(H + (size_t)row0 * DD);
    float4* Hsm4 = reinterpret_cast<float4*>(Hsm);
    const int maxv = (n - row0) * (DD / 4);
#pragma unroll
    for (int i = 0; i < (GROWS * DD / 4) / 128; i++) {  // 8
        int idx = i * 128 + tid;
        float4 v = make_float4(0.f, 0.f, 0.f, 0.f);
        if (idx < maxv) v = H4[idx];
        if (RELU) {
            v.x = fmaxf(v.x, 0.f); v.y = fmaxf(v.y, 0.f);
            v.z = fmaxf(v.z, 0.f); v.w = fmaxf(v.w, 0.f);
        }
        Hsm4[idx] = v;
    }
    __syncthreads();

    float acc[GROWS];
#pragma unroll
    for (int r = 0; r < GROWS; r++) acc[r] = 0.f;

#pragma unroll 1
    for (int k = 0; k < DD; k += 4) {
        const float w0 = Wsm[(k + 0) * DD + tid];
        const float w1 = Wsm[(k + 1) * DD + tid];
        const float w2 = Wsm[(k + 2) * DD + tid];
        const float w3 = Wsm[(k + 3) * DD + tid];
#pragma unroll
        for (int r = 0; r < GROWS; r++) {
            float4 h = reinterpret_cast<const float4*>(Hsm + r * DD)[k >> 2];
            acc[r] = fmaf(h.w, w3, fmaf(h.z, w2, fmaf(h.y, w1, fmaf(h.x, w0, acc[r]))));
        }
    }

    const float bv = bias[tid];
#pragma unroll
    for (int r = 0; r < GROWS; r++) {
        int row = row0 + r;
        if (row < n) {
            float a = acc[r];
            hw[(size_t)row * DD + tid] = a;
            float di = dinv[row];
            float v = fmaf(a, di * di, bv);
            if (ADDX) v += xres[(size_t)row * DD + tid];
            agg[(size_t)row * DD + tid] = v;
        }
    }
}

// ---------------------------------------------------------------------------
// Scatter-add: agg[dst] += hw[src] * norm[e].
// One warp per edge; lane handles a float4 slice (32*16B = full 512B row).
// red.global (no-return) vector atomics — 1 instr per 16B.
// ---------------------------------------------------------------------------
__global__ void k_scatter(const float* __restrict__ hw, const float* __restrict__ norm,
                          const int* __restrict__ src, const int* __restrict__ dst,
                          float* __restrict__ agg, int e) {
    long long t = (long long)blockIdx.x * blockDim.x + threadIdx.x;
    int edge = (int)(t >> 5);
    if (edge >= e) return;
    int c = ((int)t & 31) << 2;

    int s = src[edge];
    int d = dst[edge];
    float nm = norm[edge];

    float4 v = *reinterpret_cast<const float4*>(hw + (size_t)s * DD + c);
    float* a = agg + (size_t)d * DD + c;
    asm volatile("red.global.add.v4.f32 [%0], {%1, %2, %3, %4};"
                 :: "l"(a), "f"(v.x * nm), "f"(v.y * nm), "f"(v.z * nm), "f"(v.w * nm)
                 : "memory");
}

// ---------------------------------------------------------------------------
extern "C" void kernel_launch(void* const* d_in, const int* in_sizes, int n_in,
                              void* d_out, int out_size) {
    const float* x  = (const float*)d_in[0];
    const int*   ei = (const int*)d_in[1];
    const float* W0 = (const float*)d_in[2];
    const float* b0 = (const float*)d_in[3];
    const float* W1 = (const float*)d_in[4];
    const float* b1 = (const float*)d_in[5];
    const float* W2 = (const float*)d_in[6];
    const float* b2 = (const float*)d_in[7];
    float* out = (float*)d_out;

    const int n = in_sizes[0] / DD;
    const int e = in_sizes[1] / 2;
    const int* src = ei;       // edge_index[0]
    const int* dst = ei + e;   // edge_index[1]

    float *d_hw, *d_agg, *d_deg, *d_dinv, *d_norm;
    cudaGetSymbolAddress((void**)&d_hw,   g_hw);
    cudaGetSymbolAddress((void**)&d_agg,  g_agg);
    cudaGetSymbolAddress((void**)&d_deg,  g_deg);
    cudaGetSymbolAddress((void**)&d_dinv, g_dinv);
    cudaGetSymbolAddress((void**)&d_norm, g_norm);

    const int smem = (DD * DD + GROWS * DD) * sizeof(float);  // 81920
    cudaFuncSetAttribute(k_gemm<false, false>, cudaFuncAttributeMaxDynamicSharedMemorySize, smem);
    cudaFuncSetAttribute(k_gemm<true,  false>, cudaFuncAttributeMaxDynamicSharedMemorySize, smem);
    cudaFuncSetAttribute(k_gemm<true,  true >, cudaFuncAttributeMaxDynamicSharedMemorySize, smem);

    const int TB = 256;
    const int nb_n = (n + TB - 1) / TB;
    const int nb_e = (e + TB - 1) / TB;
    const int nb_gemm = (n + GROWS - 1) / GROWS;
    const long long scat_threads = (long long)e * 32;
    const int nb_scat = (int)((scat_threads + TB - 1) / TB);

    // degree + symmetric norm (once; reused by all 3 layers)
    k_init_deg<<<nb_n, TB>>>(d_deg, n);
    k_count_deg<<<nb_e, TB>>>(dst, d_deg, e);
    k_dinv<<<nb_n, TB>>>(d_deg, d_dinv, n);
    k_norm<<<nb_e, TB>>>(src, dst, d_dinv, d_norm, e);

    // Layer 0: h = x
    k_gemm<false, false><<<nb_gemm, 128, smem>>>(x, W0, b0, d_dinv, nullptr, d_hw, d_agg, n);
    k_scatter<<<nb_scat, TB>>>(d_hw, d_norm, src, dst, d_agg, e);

    // Layer 1: h = relu(agg)
    k_gemm<true, false><<<nb_gemm, 128, smem>>>(d_agg, W1, b1, d_dinv, nullptr, d_hw, d_agg, n);
    k_scatter<<<nb_scat, TB>>>(d_hw, d_norm, src, dst, d_agg, e);

    // Layer 2: h = relu(agg); residual +x folded into init; result -> d_out
    k_gemm<true, true><<<nb_gemm, 128, smem>>>(d_agg, W2, b2, d_dinv, x, d_hw, out, n);
    k_scatter<<<nb_scat, TB>>>(d_hw, d_norm, src, dst, out, e);
}

// round 3
// speedup vs baseline: 1.7975x; 1.7975x over previous
#include <cuda_runtime.h>
#include <math.h>

#define NN 50000
#define EE 800000
#define DD 128
#define GROWS 64
#define SCAN_B 1024

// Scratch (allocation-free rule: __device__ globals)
__device__ float g_hws[(size_t)NN * DD];  // (h @ W) * dinv[row]
__device__ float g_agg[(size_t)NN * DD];  // layer output / next-layer input
__device__ int   g_count[NN];
__device__ float g_dinv[NN];
__device__ int   g_rowptr[NN + 1];
__device__ int   g_cursor[NN];
__device__ int   g_adj[EE];               // src node per CSR slot (grouped by dst)
__device__ int   g_partials[64];

// ---------------------------------------------------------------------------
// CSR build: count -> scan -> fill.  deg = count+1 (self-loop).
// ---------------------------------------------------------------------------
__global__ void k_zero(int* c, int n) {
    int i = blockIdx.x * blockDim.x + threadIdx.x;
    if (i < n) c[i] = 0;
}

__global__ void k_count(const int* __restrict__ dst, int* __restrict__ count, int e) {
    int i = blockIdx.x * blockDim.x + threadIdx.x;
    if (i < e) atomicAdd(&count[dst[i]], 1);
}

__global__ void k_dinv(const int* __restrict__ count, float* __restrict__ dinv, int n) {
    int i = blockIdx.x * blockDim.x + threadIdx.x;
    if (i < n) dinv[i] = rsqrtf((float)count[i] + 1.0f);
}

// Per-chunk exclusive scan (Hillis-Steele), chunk totals to partials.
__global__ void k_scan_chunks(const int* __restrict__ count, int* __restrict__ rowptr,
                              int* __restrict__ partials, int n) {
    __shared__ int s[SCAN_B];
    int t = threadIdx.x;
    int i = blockIdx.x * SCAN_B + t;
    int v = (i < n) ? count[i] : 0;
    s[t] = v;
    __syncthreads();
#pragma unroll
    for (int off = 1; off < SCAN_B; off <<= 1) {
        int tmp = (t >= off) ? s[t - off] : 0;
        __syncthreads();
        s[t] += tmp;
        __syncthreads();
    }
    if (i < n) rowptr[i] = s[t] - v;  // exclusive
    if (t == SCAN_B - 1) partials[blockIdx.x] = s[t];
}

__global__ void k_scan_partials(int* partials, int nchunks) {
    __shared__ int s[64];
    int t = threadIdx.x;
    int v = (t < nchunks) ? partials[t] : 0;
    s[t] = v;
    __syncthreads();
#pragma unroll
    for (int off = 1; off < 64; off <<= 1) {
        int tmp = (t >= off) ? s[t - off] : 0;
        __syncthreads();
        s[t] += tmp;
        __syncthreads();
    }
    if (t < nchunks) partials[t] = s[t] - v;  // exclusive
}

__global__ void k_scan_finish(int* __restrict__ rowptr, int* __restrict__ cursor,
                              const int* __restrict__ partials, int n, int e) {
    int i = blockIdx.x * blockDim.x + threadIdx.x;
    if (i < n) {
        int r = rowptr[i] + partials[i / SCAN_B];
        rowptr[i] = r;
        cursor[i] = r;
    }
    if (i == 0) rowptr[n] = e;
}

__global__ void k_fill(const int* __restrict__ src, const int* __restrict__ dst,
                       int* __restrict__ cursor, int* __restrict__ adj, int e) {
    int i = blockIdx.x * blockDim.x + threadIdx.x;
    if (i < e) {
        int pos = atomicAdd(&cursor[dst[i]], 1);
        adj[pos] = src[i];
    }
}

// ---------------------------------------------------------------------------
// GEMM: hws[row] = (relu?(H[row]) @ W) * dinv[row].   128 threads = 1 output
// column each; GROWS rows per block with register accumulators.
// ---------------------------------------------------------------------------
template <bool RELU>
__global__ void __launch_bounds__(128, 1)
k_gemm(const float* __restrict__ H, const float* __restrict__ W,
       const float* __restrict__ dinv, float* __restrict__ hws, int n) {
    extern __shared__ float sm[];
    float* Wsm = sm;              // 128*128 = 64KB
    float* Hsm = sm + DD * DD;    // GROWS*128 = 32KB
    const int tid = threadIdx.x;
    const int row0 = blockIdx.x * GROWS;

    const float4* W4 = reinterpret_cast<const float4*>(W);
    float4* Wsm4 = reinterpret_cast<float4*>(Wsm);
#pragma unroll
    for (int i = 0; i < (DD * DD / 4) / 128; i++)
        Wsm4[i * 128 + tid] = W4[i * 128 + tid];

    const float4* H4 = reinterpret_cast<const float4*>(H + (size_t)row0 * DD);
    float4* Hsm4 = reinterpret_cast<float4*>(Hsm);
    const int maxv = (n - row0) * (DD / 4);
#pragma unroll
    for (int i = 0; i < (GROWS * DD / 4) / 128; i++) {
        int idx = i * 128 + tid;
        float4 v = make_float4(0.f, 0.f, 0.f, 0.f);
        if (idx < maxv) v = H4[idx];
        if (RELU) {
            v.x = fmaxf(v.x, 0.f); v.y = fmaxf(v.y, 0.f);
            v.z = fmaxf(v.z, 0.f); v.w = fmaxf(v.w, 0.f);
        }
        Hsm4[idx] = v;
    }
    __syncthreads();

    float acc[GROWS];
#pragma unroll
    for (int r = 0; r < GROWS; r++) acc[r] = 0.f;

#pragma unroll 1
    for (int k = 0; k < DD; k += 4) {
        const float w0 = Wsm[(k + 0) * DD + tid];
        const float w1 = Wsm[(k + 1) * DD + tid];
        const float w2 = Wsm[(k + 2) * DD + tid];
        const float w3 = Wsm[(k + 3) * DD + tid];
#pragma unroll
        for (int r = 0; r < GROWS; r++) {
            float4 h = reinterpret_cast<const float4*>(Hsm + r * DD)[k >> 2];
            acc[r] = fmaf(h.w, w3, fmaf(h.z, w2, fmaf(h.y, w1, fmaf(h.x, w0, acc[r]))));
        }
    }

#pragma unroll
    for (int r = 0; r < GROWS; r++) {
        int row = row0 + r;
        if (row < n)
            hws[(size_t)row * DD + tid] = acc[r] * dinv[row];
    }
}

// ---------------------------------------------------------------------------
// Pull-mode aggregate: out[d] = dinv[d]*(hws[d] + sum_{s in in(d)} hws[s]) + b (+x)
// One warp per node; lane = float4 column slice. No atomics.
// ---------------------------------------------------------------------------
template <bool ADDX>
__global__ void k_aggregate(const float* __restrict__ hws, const int* __restrict__ rowptr,
                            const int* __restrict__ adj, const float* __restrict__ dinv,
                            const float* __restrict__ bias, const float* __restrict__ xres,
                            float* __restrict__ out, int n) {
    int w = (blockIdx.x * blockDim.x + threadIdx.x) >> 5;
    if (w >= n) return;
    int lane = threadIdx.x & 31;

    const float4* base = reinterpret_cast<const float4*>(hws);
    float4 acc = base[(size_t)w * 32 + lane];  // self-loop term
    float4 acc2 = make_float4(0.f, 0.f, 0.f, 0.f);

    int j = rowptr[w];
    const int jend = rowptr[w + 1];
    for (; j + 1 < jend; j += 2) {
        int sA = __ldg(&adj[j]);
        int sB = __ldg(&adj[j + 1]);
        float4 a = base[(size_t)sA * 32 + lane];
        float4 b = base[(size_t)sB * 32 + lane];
        acc.x += a.x; acc.y += a.y; acc.z += a.z; acc.w += a.w;
        acc2.x += b.x; acc2.y += b.y; acc2.z += b.z; acc2.w += b.w;
    }
    if (j < jend) {
        int sA = __ldg(&adj[j]);
        float4 a = base[(size_t)sA * 32 + lane];
        acc.x += a.x; acc.y += a.y; acc.z += a.z; acc.w += a.w;
    }
    acc.x += acc2.x; acc.y += acc2.y; acc.z += acc2.z; acc.w += acc2.w;

    const float di = dinv[w];
    float4 b4 = reinterpret_cast<const float4*>(bias)[lane];
    float4 o;
    o.x = fmaf(acc.x, di, b4.x);
    o.y = fmaf(acc.y, di, b4.y);
    o.z = fmaf(acc.z, di, b4.z);
    o.w = fmaf(acc.w, di, b4.w);
    if (ADDX) {
        float4 xr = reinterpret_cast<const float4*>(xres)[(size_t)w * 32 + lane];
        o.x += xr.x; o.y += xr.y; o.z += xr.z; o.w += xr.w;
    }
    reinterpret_cast<float4*>(out)[(size_t)w * 32 + lane] = o;
}

// ---------------------------------------------------------------------------
extern "C" void kernel_launch(void* const* d_in, const int* in_sizes, int n_in,
                              void* d_out, int out_size) {
    const float* x  = (const float*)d_in[0];
    const int*   ei = (const int*)d_in[1];
    const float* W0 = (const float*)d_in[2];
    const float* b0 = (const float*)d_in[3];
    const float* W1 = (const float*)d_in[4];
    const float* b1 = (const float*)d_in[5];
    const float* W2 = (const float*)d_in[6];
    const float* b2 = (const float*)d_in[7];
    float* out = (float*)d_out;

    const int n = in_sizes[0] / DD;
    const int e = in_sizes[1] / 2;
    const int* src = ei;
    const int* dst = ei + e;

    float *d_hws, *d_agg, *d_dinv;
    int *d_count, *d_rowptr, *d_cursor, *d_adj, *d_partials;
    cudaGetSymbolAddress((void**)&d_hws, g_hws);
    cudaGetSymbolAddress((void**)&d_agg, g_agg);
    cudaGetSymbolAddress((void**)&d_dinv, g_dinv);
    cudaGetSymbolAddress((void**)&d_count, g_count);
    cudaGetSymbolAddress((void**)&d_rowptr, g_rowptr);
    cudaGetSymbolAddress((void**)&d_cursor, g_cursor);
    cudaGetSymbolAddress((void**)&d_adj, g_adj);
    cudaGetSymbolAddress((void**)&d_partials, g_partials);

    const int smem = (DD * DD + GROWS * DD) * sizeof(float);  // 96KB
    cudaFuncSetAttribute(k_gemm<false>, cudaFuncAttributeMaxDynamicSharedMemorySize, smem);
    cudaFuncSetAttribute(k_gemm<true>,  cudaFuncAttributeMaxDynamicSharedMemorySize, smem);

    const int TB = 256;
    const int nb_n = (n + TB - 1) / TB;
    const int nb_e = (e + TB - 1) / TB;
    const int nb_gemm = (n + GROWS - 1) / GROWS;
    const int nchunks = (n + SCAN_B - 1) / SCAN_B;
    const long long agg_threads = (long long)n * 32;
    const int nb_agg = (int)((agg_threads + TB - 1) / TB);

    // CSR build (by dst) + dinv
    k_zero<<<nb_n, TB>>>(d_count, n);
    k_count<<<nb_e, TB>>>(dst, d_count, e);
    k_dinv<<<nb_n, TB>>>(d_count, d_dinv, n);
    k_scan_chunks<<<nchunks, SCAN_B>>>(d_count, d_rowptr, d_partials, n);
    k_scan_partials<<<1, 64>>>(d_partials, nchunks);
    k_scan_finish<<<nb_n, TB>>>(d_rowptr, d_cursor, d_partials, n, e);
    k_fill<<<nb_e, TB>>>(src, dst, d_cursor, d_adj, e);

    // Layer 0
    k_gemm<false><<<nb_gemm, 128, smem>>>(x, W0, d_dinv, d_hws, n);
    k_aggregate<false><<<nb_agg, TB>>>(d_hws, d_rowptr, d_adj, d_dinv, b0, nullptr, d_agg, n);
    // Layer 1
    k_gemm<true><<<nb_gemm, 128, smem>>>(d_agg, W1, d_dinv, d_hws, n);
    k_aggregate<false><<<nb_agg, TB>>>(d_hws, d_rowptr, d_adj, d_dinv, b1, nullptr, d_agg, n);
    // Layer 2 (residual +x, write d_out)
    k_gemm<true><<<nb_gemm, 128, smem>>>(d_agg, W2, d_dinv, d_hws, n);
    k_aggregate<true><<<nb_agg, TB>>>(d_hws, d_rowptr, d_adj, d_dinv, b2, x, out, n);
}

// round 6
// speedup vs baseline: 3.0577x; 1.7011x over previous
#include <cuda_runtime.h>
#include <cuda_bf16.h>
#include <math.h>
#include <cstdint>

#define NN 50000
#define EE 800000
#define DD 128
#define SCAN_B 1024
#define PAD 272                 // padded smem row stride (bytes): conflict-free ldmatrix
#define SA_H 0
#define SA_L 34816
#define SW_H 69632
#define SW_L 104448
#define SM_TOT 139264

// ---- scratch (__device__ globals; allocation-free rule) ----
__device__ float g_hws[(size_t)NN * DD];
__device__ float g_agg[(size_t)NN * DD];
__device__ int   g_count[NN];
__device__ float g_dinv[NN];
__device__ int   g_rowptr[NN + 1];
__device__ int   g_cursor[NN];
__device__ int   g_adj[EE];
__device__ int   g_partials[64];
__device__ __nv_bfloat16 g_wh[3 * DD * DD];  // W^T hi  ([n][k] row-major)
__device__ __nv_bfloat16 g_wl[3 * DD * DD];  // W^T lo

// ---- helpers ----
__device__ __forceinline__ uint32_t smem_u32(const void* p) {
    uint32_t a;
    asm("{ .reg .u64 t; cvta.to.shared.u64 t, %1; cvt.u32.u64 %0, t; }" : "=r"(a) : "l"(p));
    return a;
}
__device__ __forceinline__ void ldsm4(uint32_t* r, uint32_t addr) {
    asm volatile("ldmatrix.sync.aligned.m8n8.x4.shared.b16 {%0,%1,%2,%3}, [%4];"
                 : "=r"(r[0]), "=r"(r[1]), "=r"(r[2]), "=r"(r[3]) : "r"(addr));
}
__device__ __forceinline__ void mma_bf16(float* c, const uint32_t* a, uint32_t b0, uint32_t b1) {
    asm volatile("mma.sync.aligned.m16n8k16.row.col.f32.bf16.bf16.f32 "
                 "{%0,%1,%2,%3}, {%4,%5,%6,%7}, {%8,%9}, {%0,%1,%2,%3};"
                 : "+f"(c[0]), "+f"(c[1]), "+f"(c[2]), "+f"(c[3])
                 : "r"(a[0]), "r"(a[1]), "r"(a[2]), "r"(a[3]), "r"(b0), "r"(b1));
}

// ---------------------------------------------------------------------------
// CSR build (by dst): count -> scan -> fill
// ---------------------------------------------------------------------------
__global__ void k_zero(int* c, int n) {
    int i = blockIdx.x * blockDim.x + threadIdx.x;
    if (i < n) c[i] = 0;
}
__global__ void k_count(const int* __restrict__ dst, int* __restrict__ count, int e) {
    int i = blockIdx.x * blockDim.x + threadIdx.x;
    if (i < e) atomicAdd(&count[dst[i]], 1);
}
__global__ void k_dinv(const int* __restrict__ count, float* __restrict__ dinv, int n) {
    int i = blockIdx.x * blockDim.x + threadIdx.x;
    if (i < n) dinv[i] = rsqrtf((float)count[i] + 1.0f);
}
__global__ void k_scan_chunks(const int* __restrict__ count, int* __restrict__ rowptr,
                              int* __restrict__ partials, int n) {
    __shared__ int s[SCAN_B];
    int t = threadIdx.x;
    int i = blockIdx.x * SCAN_B + t;
    int v = (i < n) ? count[i] : 0;
    s[t] = v;
    __syncthreads();
#pragma unroll
    for (int off = 1; off < SCAN_B; off <<= 1) {
        int tmp = (t >= off) ? s[t - off] : 0;
        __syncthreads();
        s[t] += tmp;
        __syncthreads();
    }
    if (i < n) rowptr[i] = s[t] - v;
    if (t == SCAN_B - 1) partials[blockIdx.x] = s[t];
}
__global__ void k_scan_partials(int* partials, int nchunks) {
    __shared__ int s[64];
    int t = threadIdx.x;
    int v = (t < nchunks) ? partials[t] : 0;
    s[t] = v;
    __syncthreads();
#pragma unroll
    for (int off = 1; off < 64; off <<= 1) {
        int tmp = (t >= off) ? s[t - off] : 0;
        __syncthreads();
        s[t] += tmp;
        __syncthreads();
    }
    if (t < nchunks) partials[t] = s[t] - v;
}
__global__ void k_scan_finish(int* __restrict__ rowptr, int* __restrict__ cursor,
                              const int* __restrict__ partials, int n, int e) {
    int i = blockIdx.x * blockDim.x + threadIdx.x;
    if (i < n) {
        int r = rowptr[i] + partials[i / SCAN_B];
        rowptr[i] = r;
        cursor[i] = r;
    }
    if (i == 0) rowptr[n] = e;
}
__global__ void k_fill(const int* __restrict__ src, const int* __restrict__ dst,
                       int* __restrict__ cursor, int* __restrict__ adj, int e) {
    int i = blockIdx.x * blockDim.x + threadIdx.x;
    if (i < e) {
        int pos = atomicAdd(&cursor[dst[i]], 1);
        adj[pos] = src[i];
    }
}

// ---------------------------------------------------------------------------
// W prep: WT[n][k] = W[k][n], split into bf16 hi/lo (row-major, 256B rows)
// ---------------------------------------------------------------------------
__global__ void k_wsplit(const float* __restrict__ W, __nv_bfloat16* __restrict__ wh,
                         __nv_bfloat16* __restrict__ wl) {
    int idx = blockIdx.x * blockDim.x + threadIdx.x;  // < 16384
    int k = idx >> 7, nn = idx & 127;
    float w = W[idx];
    __nv_bfloat16 h = __float2bfloat16(w);
    __nv_bfloat16 l = __float2bfloat16(w - __bfloat162float(h));
    wh[nn * DD + k] = h;
    wl[nn * DD + k] = l;
}

// ---------------------------------------------------------------------------
// Tensor-core GEMM (mma.sync bf16, 3-pass split, fp32 accum):
//   hws[row] = (relu?(H[row]) @ W) * dinv[row]
// 256 threads / 8 warps; 128 rows per block; warp = 16 rows x 128 cols.
// ---------------------------------------------------------------------------
template <bool RELU>
__global__ void __launch_bounds__(256, 1)
k_gemm_mma(const float* __restrict__ H, const __nv_bfloat16* __restrict__ wth,
           const __nv_bfloat16* __restrict__ wtl, const float* __restrict__ dinv,
           float* __restrict__ hws, int n) {
    extern __shared__ char smem[];
    const int tid = threadIdx.x;
    const int row0 = blockIdx.x * 128;

    // Stage W^T hi/lo into padded smem (verbatim rows: 16 x 16B chunks per row)
    {
        const float4* wh4 = reinterpret_cast<const float4*>(wth);
        const float4* wl4 = reinterpret_cast<const float4*>(wtl);
#pragma unroll
        for (int i = 0; i < 8; i++) {
            int chunk = i * 256 + tid;           // 2048 chunks
            int r = chunk >> 4, c = chunk & 15;
            *reinterpret_cast<float4*>(smem + SW_H + r * PAD + c * 16) = wh4[chunk];
            *reinterpret_cast<float4*>(smem + SW_L + r * PAD + c * 16) = wl4[chunk];
        }
    }
    // Stage A hi/lo (fp32 -> bf16 split, ReLU fused, OOB rows -> 0)
    {
        const float4* H4 = reinterpret_cast<const float4*>(H);
#pragma unroll
        for (int i = 0; i < 16; i++) {
            int chunk = i * 256 + tid;           // 4096 chunks (128 rows x 32)
            int r = chunk >> 5, c = chunk & 31;
            int row = row0 + r;
            float4 v = make_float4(0.f, 0.f, 0.f, 0.f);
            if (row < n) v = H4[(size_t)row * 32 + c];
            if (RELU) {
                v.x = fmaxf(v.x, 0.f); v.y = fmaxf(v.y, 0.f);
                v.z = fmaxf(v.z, 0.f); v.w = fmaxf(v.w, 0.f);
            }
            __nv_bfloat162 h01 = __float22bfloat162_rn(make_float2(v.x, v.y));
            __nv_bfloat162 h23 = __float22bfloat162_rn(make_float2(v.z, v.w));
            float2 hf01 = __bfloat1622float2(h01);
            float2 hf23 = __bfloat1622float2(h23);
            __nv_bfloat162 l01 = __float22bfloat162_rn(make_float2(v.x - hf01.x, v.y - hf01.y));
            __nv_bfloat162 l23 = __float22bfloat162_rn(make_float2(v.z - hf23.x, v.w - hf23.y));
            uint2 hp, lp;
            hp.x = *reinterpret_cast<uint32_t*>(&h01);
            hp.y = *reinterpret_cast<uint32_t*>(&h23);
            lp.x = *reinterpret_cast<uint32_t*>(&l01);
            lp.y = *reinterpret_cast<uint32_t*>(&l23);
            *reinterpret_cast<uint2*>(smem + SA_H + r * PAD + c * 8) = hp;
            *reinterpret_cast<uint2*>(smem + SA_L + r * PAD + c * 8) = lp;
        }
    }
    __syncthreads();

    const uint32_t sb = smem_u32(smem);
    const int w = tid >> 5, lane = tid & 31;

    // ldmatrix per-lane base addresses
    const uint32_t aAddrH = sb + SA_H +
        (uint32_t)(w * 16 + ((lane >> 3) & 1) * 8 + (lane & 7)) * PAD + (uint32_t)(lane >> 4) * 16;
    const uint32_t aAddrL = aAddrH + (SA_L - SA_H);
    const uint32_t bAddrH = sb + SW_H +
        (uint32_t)(((lane >> 4) & 1) * 8 + (lane & 7)) * PAD + (uint32_t)((lane >> 3) & 1) * 16;

    float c[16][4];
#pragma unroll
    for (int t = 0; t < 16; t++)
#pragma unroll
        for (int j = 0; j < 4; j++) c[t][j] = 0.f;

#pragma unroll
    for (int kk = 0; kk < 8; kk++) {
        uint32_t ah[4], al[4];
        ldsm4(ah, aAddrH + kk * 32);
        ldsm4(al, aAddrL + kk * 32);
#pragma unroll
        for (int np = 0; np < 8; np++) {
            uint32_t bh[4], bl[4];
            const uint32_t ba = bAddrH + (uint32_t)np * (16 * PAD) + kk * 32;
            ldsm4(bh, ba);
            ldsm4(bl, ba + (SW_L - SW_H));
            mma_bf16(c[np * 2 + 0], ah, bh[0], bh[1]);   // hi*hi
            mma_bf16(c[np * 2 + 1], ah, bh[2], bh[3]);
            mma_bf16(c[np * 2 + 0], ah, bl[0], bl[1]);   // hi*lo
            mma_bf16(c[np * 2 + 1], ah, bl[2], bl[3]);
            mma_bf16(c[np * 2 + 0], al, bh[0], bh[1]);   // lo*hi
            mma_bf16(c[np * 2 + 1], al, bh[2], bh[3]);
        }
    }

    // Epilogue: scale by dinv, store (frag: c0c1 row g, c2c3 row g+8, cols t*8+tg*2)
    const int g = lane >> 2, tg = lane & 3;
    const int rowA = row0 + w * 16 + g;
    const int rowB = rowA + 8;
    const float diA = (rowA < n) ? dinv[rowA] : 0.f;
    const float diB = (rowB < n) ? dinv[rowB] : 0.f;
#pragma unroll
    for (int t = 0; t < 16; t++) {
        const int col = t * 8 + tg * 2;
        if (rowA < n)
            *reinterpret_cast<float2*>(hws + (size_t)rowA * DD + col) =
                make_float2(c[t][0] * diA, c[t][1] * diA);
        if (rowB < n)
            *reinterpret_cast<float2*>(hws + (size_t)rowB * DD + col) =
                make_float2(c[t][2] * diB, c[t][3] * diB);
    }
}

// ---------------------------------------------------------------------------
// Pull-mode aggregate: out[d] = dinv[d]*(hws[d] + sum_{s in in(d)} hws[s]) + b (+x)
// ---------------------------------------------------------------------------
template <bool ADDX>
__global__ void k_aggregate(const float* __restrict__ hws, const int* __restrict__ rowptr,
                            const int* __restrict__ adj, const float* __restrict__ dinv,
                            const float* __restrict__ bias, const float* __restrict__ xres,
                            float* __restrict__ out, int n) {
    int w = (blockIdx.x * blockDim.x + threadIdx.x) >> 5;
    if (w >= n) return;
    int lane = threadIdx.x & 31;

    const float4* base = reinterpret_cast<const float4*>(hws);
    float4 acc = base[(size_t)w * 32 + lane];
    float4 acc2 = make_float4(0.f, 0.f, 0.f, 0.f);

    int j = rowptr[w];
    const int jend = rowptr[w + 1];
    for (; j + 1 < jend; j += 2) {
        int sA = __ldg(&adj[j]);
        int sB = __ldg(&adj[j + 1]);
        float4 a = base[(size_t)sA * 32 + lane];
        float4 b = base[(size_t)sB * 32 + lane];
        acc.x += a.x; acc.y += a.y; acc.z += a.z; acc.w += a.w;
        acc2.x += b.x; acc2.y += b.y; acc2.z += b.z; acc2.w += b.w;
    }
    if (j < jend) {
        int sA = __ldg(&adj[j]);
        float4 a = base[(size_t)sA * 32 + lane];
        acc.x += a.x; acc.y += a.y; acc.z += a.z; acc.w += a.w;
    }
    acc.x += acc2.x; acc.y += acc2.y; acc.z += acc2.z; acc.w += acc2.w;

    const float di = dinv[w];
    float4 b4 = reinterpret_cast<const float4*>(bias)[lane];
    float4 o;
    o.x = fmaf(acc.x, di, b4.x);
    o.y = fmaf(acc.y, di, b4.y);
    o.z = fmaf(acc.z, di, b4.z);
    o.w = fmaf(acc.w, di, b4.w);
    if (ADDX) {
        float4 xr = reinterpret_cast<const float4*>(xres)[(size_t)w * 32 + lane];
        o.x += xr.x; o.y += xr.y; o.z += xr.z; o.w += xr.w;
    }
    reinterpret_cast<float4*>(out)[(size_t)w * 32 + lane] = o;
}

// ---------------------------------------------------------------------------
extern "C" void kernel_launch(void* const* d_in, const int* in_sizes, int n_in,
                              void* d_out, int out_size) {
    const float* x  = (const float*)d_in[0];
    const int*   ei = (const int*)d_in[1];
    const float* W0 = (const float*)d_in[2];
    const float* b0 = (const float*)d_in[3];
    const float* W1 = (const float*)d_in[4];
    const float* b1 = (const float*)d_in[5];
    const float* W2 = (const float*)d_in[6];
    const float* b2 = (const float*)d_in[7];
    float* out = (float*)d_out;

    const int n = in_sizes[0] / DD;
    const int e = in_sizes[1] / 2;
    const int* src = ei;
    const int* dst = ei + e;

    float *d_hws, *d_agg, *d_dinv;
    int *d_count, *d_rowptr, *d_cursor, *d_adj, *d_partials;
    __nv_bfloat16 *d_wh, *d_wl;
    cudaGetSymbolAddress((void**)&d_hws, g_hws);
    cudaGetSymbolAddress((void**)&d_agg, g_agg);
    cudaGetSymbolAddress((void**)&d_dinv, g_dinv);
    cudaGetSymbolAddress((void**)&d_count, g_count);
    cudaGetSymbolAddress((void**)&d_rowptr, g_rowptr);
    cudaGetSymbolAddress((void**)&d_cursor, g_cursor);
    cudaGetSymbolAddress((void**)&d_adj, g_adj);
    cudaGetSymbolAddress((void**)&d_partials, g_partials);
    cudaGetSymbolAddress((void**)&d_wh, g_wh);
    cudaGetSymbolAddress((void**)&d_wl, g_wl);

    cudaFuncSetAttribute(k_gemm_mma<false>, cudaFuncAttributeMaxDynamicSharedMemorySize, SM_TOT);
    cudaFuncSetAttribute(k_gemm_mma<true>,  cudaFuncAttributeMaxDynamicSharedMemorySize, SM_TOT);

    const int TB = 256;
    const int nb_n = (n + TB - 1) / TB;
    const int nb_e = (e + TB - 1) / TB;
    const int nb_gemm = (n + 127) / 128;
    const int nchunks = (n + SCAN_B - 1) / SCAN_B;
    const long long agg_threads = (long long)n * 32;
    const int nb_agg = (int)((agg_threads + TB - 1) / TB);

    // CSR build + dinv
    k_zero<<<nb_n, TB>>>(d_count, n);
    k_count<<<nb_e, TB>>>(dst, d_count, e);
    k_dinv<<<nb_n, TB>>>(d_count, d_dinv, n);
    k_scan_chunks<<<nchunks, SCAN_B>>>(d_count, d_rowptr, d_partials, n);
    k_scan_partials<<<1, 64>>>(d_partials, nchunks);
    k_scan_finish<<<nb_n, TB>>>(d_rowptr, d_cursor, d_partials, n, e);
    k_fill<<<nb_e, TB>>>(src, dst, d_cursor, d_adj, e);

    // W^T hi/lo
    k_wsplit<<<64, 256>>>(W0, d_wh + 0 * DD * DD, d_wl + 0 * DD * DD);
    k_wsplit<<<64, 256>>>(W1, d_wh + 1 * DD * DD, d_wl + 1 * DD * DD);
    k_wsplit<<<64, 256>>>(W2, d_wh + 2 * DD * DD, d_wl + 2 * DD * DD);

    // Layer 0
    k_gemm_mma<false><<<nb_gemm, 256, SM_TOT>>>(x, d_wh, d_wl, d_dinv, d_hws, n);
    k_aggregate<false><<<nb_agg, TB>>>(d_hws, d_rowptr, d_adj, d_dinv, b0, nullptr, d_agg, n);
    // Layer 1
    k_gemm_mma<true><<<nb_gemm, 256, SM_TOT>>>(d_agg, d_wh + DD * DD, d_wl + DD * DD, d_dinv, d_hws, n);
    k_aggregate<false><<<nb_agg, TB>>>(d_hws, d_rowptr, d_adj, d_dinv, b1, nullptr, d_agg, n);
    // Layer 2 (+x residual, write d_out)
    k_gemm_mma<true><<<nb_gemm, 256, SM_TOT>>>(d_agg, d_wh + 2 * DD * DD, d_wl + 2 * DD * DD, d_dinv, d_hws, n);
    k_aggregate<true><<<nb_agg, TB>>>(d_hws, d_rowptr, d_adj, d_dinv, b2, x, out, n);
}

// round 7
// speedup vs baseline: 3.2979x; 1.0786x over previous
#include <cuda_runtime.h>
#include <cuda_bf16.h>
#include <cuda_fp16.h>
#include <math.h>
#include <cstdint>

#define NN 50000
#define EE 800000
#define DD 128
#define SCAN_B 1024
#define PAD 272                 // padded smem row stride (bytes): conflict-free ldmatrix
#define SA_H 0
#define SA_L 34816
#define SW_H 69632
#define SW_L 104448
#define SM_TOT 139264

// ---- scratch (__device__ globals; allocation-free rule) ----
__device__ __half g_hwsh[(size_t)NN * DD];   // (h@W)*dinv, fp16 (gather payload)
__device__ float g_agg[(size_t)NN * DD];
__device__ int   g_count[NN];
__device__ float g_dinv[NN];
__device__ int   g_rowptr[NN + 1];
__device__ int   g_cursor[NN];
__device__ int   g_adj[EE];
__device__ int   g_partials[64];
__device__ __nv_bfloat16 g_wh[3 * DD * DD];  // W^T hi  ([n][k] row-major)
__device__ __nv_bfloat16 g_wl[3 * DD * DD];  // W^T lo

// ---- helpers ----
__device__ __forceinline__ uint32_t smem_u32(const void* p) {
    uint32_t a;
    asm("{ .reg .u64 t; cvta.to.shared.u64 t, %1; cvt.u32.u64 %0, t; }" : "=r"(a) : "l"(p));
    return a;
}
__device__ __forceinline__ void ldsm4(uint32_t* r, uint32_t addr) {
    asm volatile("ldmatrix.sync.aligned.m8n8.x4.shared.b16 {%0,%1,%2,%3}, [%4];"
                 : "=r"(r[0]), "=r"(r[1]), "=r"(r[2]), "=r"(r[3]) : "r"(addr));
}
__device__ __forceinline__ void mma_bf16(float* c, const uint32_t* a, uint32_t b0, uint32_t b1) {
    asm volatile("mma.sync.aligned.m16n8k16.row.col.f32.bf16.bf16.f32 "
                 "{%0,%1,%2,%3}, {%4,%5,%6,%7}, {%8,%9}, {%0,%1,%2,%3};"
                 : "+f"(c[0]), "+f"(c[1]), "+f"(c[2]), "+f"(c[3])
                 : "r"(a[0]), "r"(a[1]), "r"(a[2]), "r"(a[3]), "r"(b0), "r"(b1));
}
__device__ __forceinline__ void add8(float* a, uint4 v) {
    const __half2* h = reinterpret_cast<const __half2*>(&v);
#pragma unroll
    for (int i = 0; i < 4; i++) {
        float2 f = __half22float2(h[i]);
        a[2 * i] += f.x;
        a[2 * i + 1] += f.y;
    }
}

// ---------------------------------------------------------------------------
// CSR build (by dst): count -> scan(+dinv) -> fill
// ---------------------------------------------------------------------------
__global__ void k_zero(int* c, int n) {
    int i = blockIdx.x * blockDim.x + threadIdx.x;
    if (i < n) c[i] = 0;
}
__global__ void k_count(const int* __restrict__ dst, int* __restrict__ count, int e) {
    int i = blockIdx.x * blockDim.x + threadIdx.x;
    if (i < e) atomicAdd(&count[dst[i]], 1);
}
__global__ void k_scan_chunks(const int* __restrict__ count, int* __restrict__ rowptr,
                              int* __restrict__ partials, float* __restrict__ dinv, int n) {
    __shared__ int s[SCAN_B];
    int t = threadIdx.x;
    int i = blockIdx.x * SCAN_B + t;
    int v = (i < n) ? count[i] : 0;
    if (i < n) dinv[i] = rsqrtf((float)v + 1.0f);   // fused dinv
    s[t] = v;
    __syncthreads();
#pragma unroll
    for (int off = 1; off < SCAN_B; off <<= 1) {
        int tmp = (t >= off) ? s[t - off] : 0;
        __syncthreads();
        s[t] += tmp;
        __syncthreads();
    }
    if (i < n) rowptr[i] = s[t] - v;
    if (t == SCAN_B - 1) partials[blockIdx.x] = s[t];
}
__global__ void k_scan_partials(int* partials, int nchunks) {
    __shared__ int s[64];
    int t = threadIdx.x;
    int v = (t < nchunks) ? partials[t] : 0;
    s[t] = v;
    __syncthreads();
#pragma unroll
    for (int off = 1; off < 64; off <<= 1) {
        int tmp = (t >= off) ? s[t - off] : 0;
        __syncthreads();
        s[t] += tmp;
        __syncthreads();
    }
    if (t < nchunks) partials[t] = s[t] - v;
}
__global__ void k_scan_finish(int* __restrict__ rowptr, int* __restrict__ cursor,
                              const int* __restrict__ partials, int n, int e) {
    int i = blockIdx.x * blockDim.x + threadIdx.x;
    if (i < n) {
        int r = rowptr[i] + partials[i / SCAN_B];
        rowptr[i] = r;
        cursor[i] = r;
    }
    if (i == 0) rowptr[n] = e;
}
__global__ void k_fill(const int* __restrict__ src, const int* __restrict__ dst,
                       int* __restrict__ cursor, int* __restrict__ adj, int e) {
    int i = blockIdx.x * blockDim.x + threadIdx.x;
    if (i < e) {
        int pos = atomicAdd(&cursor[dst[i]], 1);
        adj[pos] = src[i];
    }
}

// ---------------------------------------------------------------------------
// W prep (all 3 layers in one launch): WT[n][k] = W[k][n], bf16 hi/lo split
// ---------------------------------------------------------------------------
__global__ void k_wsplit(const float* __restrict__ W0, const float* __restrict__ W1,
                         const float* __restrict__ W2, __nv_bfloat16* __restrict__ wh,
                         __nv_bfloat16* __restrict__ wl) {
    int gi = blockIdx.x * blockDim.x + threadIdx.x;  // < 3*16384
    int layer = gi >> 14, idx = gi & 16383;
    const float* W = (layer == 0) ? W0 : (layer == 1) ? W1 : W2;
    int k = idx >> 7, nn = idx & 127;
    float w = W[idx];
    __nv_bfloat16 h = __float2bfloat16(w);
    __nv_bfloat16 l = __float2bfloat16(w - __bfloat162float(h));
    wh[layer * DD * DD + nn * DD + k] = h;
    wl[layer * DD * DD + nn * DD + k] = l;
}

// ---------------------------------------------------------------------------
// Tensor-core GEMM (mma.sync bf16, 3-pass split, fp32 accum):
//   hwsh[row] = half((relu?(H[row]) @ W) * dinv[row])
// 256 threads / 8 warps; 128 rows per block; warp = 16 rows x 128 cols.
// ---------------------------------------------------------------------------
template <bool RELU>
__global__ void __launch_bounds__(256, 1)
k_gemm_mma(const float* __restrict__ H, const __nv_bfloat16* __restrict__ wth,
           const __nv_bfloat16* __restrict__ wtl, const float* __restrict__ dinv,
           __half* __restrict__ hws, int n) {
    extern __shared__ char smem[];
    const int tid = threadIdx.x;
    const int row0 = blockIdx.x * 128;

    // Stage W^T hi/lo into padded smem
    {
        const float4* wh4 = reinterpret_cast<const float4*>(wth);
        const float4* wl4 = reinterpret_cast<const float4*>(wtl);
#pragma unroll
        for (int i = 0; i < 8; i++) {
            int chunk = i * 256 + tid;
            int r = chunk >> 4, c = chunk & 15;
            *reinterpret_cast<float4*>(smem + SW_H + r * PAD + c * 16) = wh4[chunk];
            *reinterpret_cast<float4*>(smem + SW_L + r * PAD + c * 16) = wl4[chunk];
        }
    }
    // Stage A hi/lo (fp32 -> bf16 split, ReLU fused, OOB rows -> 0)
    {
        const float4* H4 = reinterpret_cast<const float4*>(H);
#pragma unroll
        for (int i = 0; i < 16; i++) {
            int chunk = i * 256 + tid;
            int r = chunk >> 5, c = chunk & 31;
            int row = row0 + r;
            float4 v = make_float4(0.f, 0.f, 0.f, 0.f);
            if (row < n) v = H4[(size_t)row * 32 + c];
            if (RELU) {
                v.x = fmaxf(v.x, 0.f); v.y = fmaxf(v.y, 0.f);
                v.z = fmaxf(v.z, 0.f); v.w = fmaxf(v.w, 0.f);
            }
            __nv_bfloat162 h01 = __float22bfloat162_rn(make_float2(v.x, v.y));
            __nv_bfloat162 h23 = __float22bfloat162_rn(make_float2(v.z, v.w));
            float2 hf01 = __bfloat1622float2(h01);
            float2 hf23 = __bfloat1622float2(h23);
            __nv_bfloat162 l01 = __float22bfloat162_rn(make_float2(v.x - hf01.x, v.y - hf01.y));
            __nv_bfloat162 l23 = __float22bfloat162_rn(make_float2(v.z - hf23.x, v.w - hf23.y));
            uint2 hp, lp;
            hp.x = *reinterpret_cast<uint32_t*>(&h01);
            hp.y = *reinterpret_cast<uint32_t*>(&h23);
            lp.x = *reinterpret_cast<uint32_t*>(&l01);
            lp.y = *reinterpret_cast<uint32_t*>(&l23);
            *reinterpret_cast<uint2*>(smem + SA_H + r * PAD + c * 8) = hp;
            *reinterpret_cast<uint2*>(smem + SA_L + r * PAD + c * 8) = lp;
        }
    }
    __syncthreads();

    const uint32_t sb = smem_u32(smem);
    const int w = tid >> 5, lane = tid & 31;

    const uint32_t aAddrH = sb + SA_H +
        (uint32_t)(w * 16 + ((lane >> 3) & 1) * 8 + (lane & 7)) * PAD + (uint32_t)(lane >> 4) * 16;
    const uint32_t aAddrL = aAddrH + (SA_L - SA_H);
    const uint32_t bAddrH = sb + SW_H +
        (uint32_t)(((lane >> 4) & 1) * 8 + (lane & 7)) * PAD + (uint32_t)((lane >> 3) & 1) * 16;

    float c[16][4];
#pragma unroll
    for (int t = 0; t < 16; t++)
#pragma unroll
        for (int j = 0; j < 4; j++) c[t][j] = 0.f;

#pragma unroll
    for (int kk = 0; kk < 8; kk++) {
        uint32_t ah[4], al[4];
        ldsm4(ah, aAddrH + kk * 32);
        ldsm4(al, aAddrL + kk * 32);
#pragma unroll
        for (int np = 0; np < 8; np++) {
            uint32_t bh[4], bl[4];
            const uint32_t ba = bAddrH + (uint32_t)np * (16 * PAD) + kk * 32;
            ldsm4(bh, ba);
            ldsm4(bl, ba + (SW_L - SW_H));
            mma_bf16(c[np * 2 + 0], ah, bh[0], bh[1]);   // hi*hi
            mma_bf16(c[np * 2 + 1], ah, bh[2], bh[3]);
            mma_bf16(c[np * 2 + 0], ah, bl[0], bl[1]);   // hi*lo
            mma_bf16(c[np * 2 + 1], ah, bl[2], bl[3]);
            mma_bf16(c[np * 2 + 0], al, bh[0], bh[1]);   // lo*hi
            mma_bf16(c[np * 2 + 1], al, bh[2], bh[3]);
        }
    }

    // Epilogue: scale by dinv, store fp16
    const int g = lane >> 2, tg = lane & 3;
    const int rowA = row0 + w * 16 + g;
    const int rowB = rowA + 8;
    const float diA = (rowA < n) ? dinv[rowA] : 0.f;
    const float diB = (rowB < n) ? dinv[rowB] : 0.f;
#pragma unroll
    for (int t = 0; t < 16; t++) {
        const int col = t * 8 + tg * 2;
        if (rowA < n) {
            __half2 hv = __floats2half2_rn(c[t][0] * diA, c[t][1] * diA);
            *reinterpret_cast<__half2*>(hws + (size_t)rowA * DD + col) = hv;
        }
        if (rowB < n) {
            __half2 hv = __floats2half2_rn(c[t][2] * diB, c[t][3] * diB);
            *reinterpret_cast<__half2*>(hws + (size_t)rowB * DD + col) = hv;
        }
    }
}

// ---------------------------------------------------------------------------
// Pull-mode aggregate (fp16 gather, fp32 accumulate):
//   out[d] = dinv[d]*(hws[d] + sum_{s in in(d)} hws[s]) + b (+x)
// Half-warp (16 lanes) per node; lane = uint4 (8 halves = 16B) slice.
// ---------------------------------------------------------------------------
template <bool ADDX>
__global__ void k_aggregate(const __half* __restrict__ hws, const int* __restrict__ rowptr,
                            const int* __restrict__ adj, const float* __restrict__ dinv,
                            const float* __restrict__ bias, const float* __restrict__ xres,
                            float* __restrict__ out, int n) {
    int w = (blockIdx.x * blockDim.x + threadIdx.x) >> 4;
    if (w >= n) return;
    const int lane = threadIdx.x & 15;

    const uint4* base = reinterpret_cast<const uint4*>(hws);  // 16 uint4 per row
    float acc0[8], acc1[8];
#pragma unroll
    for (int i = 0; i < 8; i++) { acc0[i] = 0.f; acc1[i] = 0.f; }
    add8(acc0, base[(size_t)w * 16 + lane]);  // self-loop

    int j = rowptr[w];
    const int jend = rowptr[w + 1];
    for (; j + 1 < jend; j += 2) {
        int sA = __ldg(&adj[j]);
        int sB = __ldg(&adj[j + 1]);
        uint4 a = base[(size_t)sA * 16 + lane];
        uint4 b = base[(size_t)sB * 16 + lane];
        add8(acc0, a);
        add8(acc1, b);
    }
    if (j < jend) add8(acc0, base[(size_t)__ldg(&adj[j]) * 16 + lane]);
#pragma unroll
    for (int i = 0; i < 8; i++) acc0[i] += acc1[i];

    const float di = dinv[w];
    const int col = lane * 8;
    float o[8];
#pragma unroll
    for (int i = 0; i < 8; i++) o[i] = fmaf(acc0[i], di, bias[col + i]);
    if (ADDX) {
        const float4* xr = reinterpret_cast<const float4*>(xres + (size_t)w * DD + col);
        float4 x0 = xr[0], x1 = xr[1];
        o[0] += x0.x; o[1] += x0.y; o[2] += x0.z; o[3] += x0.w;
        o[4] += x1.x; o[5] += x1.y; o[6] += x1.z; o[7] += x1.w;
    }
    float4* op = reinterpret_cast<float4*>(out + (size_t)w * DD + col);
    op[0] = make_float4(o[0], o[1], o[2], o[3]);
    op[1] = make_float4(o[4], o[5], o[6], o[7]);
}

// ---------------------------------------------------------------------------
extern "C" void kernel_launch(void* const* d_in, const int* in_sizes, int n_in,
                              void* d_out, int out_size) {
    const float* x  = (const float*)d_in[0];
    const int*   ei = (const int*)d_in[1];
    const float* W0 = (const float*)d_in[2];
    const float* b0 = (const float*)d_in[3];
    const float* W1 = (const float*)d_in[4];
    const float* b1 = (const float*)d_in[5];
    const float* W2 = (const float*)d_in[6];
    const float* b2 = (const float*)d_in[7];
    float* out = (float*)d_out;

    const int n = in_sizes[0] / DD;
    const int e = in_sizes[1] / 2;
    const int* src = ei;
    const int* dst = ei + e;

    float *d_agg, *d_dinv;
    __half* d_hws;
    int *d_count, *d_rowptr, *d_cursor, *d_adj, *d_partials;
    __nv_bfloat16 *d_wh, *d_wl;
    cudaGetSymbolAddress((void**)&d_hws, g_hwsh);
    cudaGetSymbolAddress((void**)&d_agg, g_agg);
    cudaGetSymbolAddress((void**)&d_dinv, g_dinv);
    cudaGetSymbolAddress((void**)&d_count, g_count);
    cudaGetSymbolAddress((void**)&d_rowptr, g_rowptr);
    cudaGetSymbolAddress((void**)&d_cursor, g_cursor);
    cudaGetSymbolAddress((void**)&d_adj, g_adj);
    cudaGetSymbolAddress((void**)&d_partials, g_partials);
    cudaGetSymbolAddress((void**)&d_wh, g_wh);
    cudaGetSymbolAddress((void**)&d_wl, g_wl);

    cudaFuncSetAttribute(k_gemm_mma<false>, cudaFuncAttributeMaxDynamicSharedMemorySize, SM_TOT);
    cudaFuncSetAttribute(k_gemm_mma<true>,  cudaFuncAttributeMaxDynamicSharedMemorySize, SM_TOT);

    const int TB = 256;
    const int nb_n = (n + TB - 1) / TB;
    const int nb_e = (e + TB - 1) / TB;
    const int nb_gemm = (n + 127) / 128;
    const int nchunks = (n + SCAN_B - 1) / SCAN_B;
    const long long agg_threads = (long long)n * 16;
    const int nb_agg = (int)((agg_threads + TB - 1) / TB);

    // CSR build + dinv
    k_zero<<<nb_n, TB>>>(d_count, n);
    k_count<<<nb_e, TB>>>(dst, d_count, e);
    k_scan_chunks<<<nchunks, SCAN_B>>>(d_count, d_rowptr, d_partials, d_dinv, n);
    k_scan_partials<<<1, 64>>>(d_partials, nchunks);
    k_scan_finish<<<nb_n, TB>>>(d_rowptr, d_cursor, d_partials, n, e);
    k_fill<<<nb_e, TB>>>(src, dst, d_cursor, d_adj, e);

    // W^T hi/lo (all 3 layers, one launch)
    k_wsplit<<<192, 256>>>(W0, W1, W2, d_wh, d_wl);

    // Layer 0
    k_gemm_mma<false><<<nb_gemm, 256, SM_TOT>>>(x, d_wh, d_wl, d_dinv, d_hws, n);
    k_aggregate<false><<<nb_agg, TB>>>(d_hws, d_rowptr, d_adj, d_dinv, b0, nullptr, d_agg, n);
    // Layer 1
    k_gemm_mma<true><<<nb_gemm, 256, SM_TOT>>>(d_agg, d_wh + DD * DD, d_wl + DD * DD, d_dinv, d_hws, n);
    k_aggregate<false><<<nb_agg, TB>>>(d_hws, d_rowptr, d_adj, d_dinv, b1, nullptr, d_agg, n);
    // Layer 2 (+x residual, write d_out)
    k_gemm_mma<true><<<nb_gemm, 256, SM_TOT>>>(d_agg, d_wh + 2 * DD * DD, d_wl + 2 * DD * DD, d_dinv, d_hws, n);
    k_aggregate<true><<<nb_agg, TB>>>(d_hws, d_rowptr, d_adj, d_dinv, b2, x, out, n);
}